// round 14
// baseline (speedup 1.0000x reference)
#include <cuda_runtime.h>
#include <math.h>

#define N_NODES 512
#define DIM 128
#define NA 192          // total anchors
#define G3 384          // 3*DIM
typedef unsigned long long ULL;

// ---------------- scratch (no allocations allowed) ----------------
__device__ float g_x[N_NODES * DIM];
__device__ float g_abn[N_NODES];
__device__ float g_tpos[N_NODES];
__device__ float g_Gi[6 * N_NODES * G3];
__device__ float g_hout[NA * 2 * DIM];
__device__ float g_abnout[NA * 2];
__device__ float g_WihT[6 * DIM * G3];   // [sd][k][row]
__device__ float g_WhhT[6 * DIM * G3];   // [sd][k][row]
__device__ int   g_pairs[96][2];         // [scale*32+pair][2], len-matched within scale
__device__ int   g_order[96];            // pair schedule, len desc

__device__ __forceinline__ float sigf(float x) { return 1.f / (1.f + __expf(-x)); }
__device__ __forceinline__ float tanhfast(float x) { return 2.f / (1.f + __expf(-2.f * x)) - 1.f; }

// ---------------- kernel 1 (fused): preprocess + GRU weight transpose ----------------
__global__ void k_pre_tr(const float* __restrict__ emb, const float* __restrict__ tp,
                         const float* __restrict__ pred, const float* __restrict__ al_p,
                         const float* __restrict__ kern,
                         const float* __restrict__ Wih, const float* __restrict__ Whh)
{
    int b = blockIdx.x;
    int t = threadIdx.x;
    if (b < 256) {
        int tid = b * 256 + t;
        if (tid < N_NODES * DIM) {
            int n = tid >> 7, d = tid & 127;
            float freq = (10.f / 127.f) * (float)d;
            g_x[tid] = emb[tid] + 0.05f * sinf(tp[n] * freq);
        }
        if (tid < N_NODES) {
            int n = tid;
            float kv[5];
            #pragma unroll
            for (int k = 0; k < 5; k++) kv[k] = kern[k];
            float sv[5];
            #pragma unroll
            for (int c = 0; c < 5; c++) {
                float acc = 0.f;
                #pragma unroll
                for (int k = 0; k < 5; k++) {
                    int nn = n + k - 2;
                    if (nn >= 0 && nn < N_NODES) acc += kv[k] * pred[nn * 5 + c];
                }
                sv[c] = acc;
            }
            float m = sv[0];
            #pragma unroll
            for (int c = 1; c < 5; c++) m = fmaxf(m, sv[c]);
            float den = 0.f;
            #pragma unroll
            for (int c = 0; c < 5; c++) den += __expf(sv[c] - m);
            g_abn[n] = __expf(sv[0] - m) / den;
            g_tpos[n] = tp[n] * al_p[0];
        }
        return;
    }
    // GRU weight transpose (tiled, coalesced both sides)
    __shared__ float s1[32][33];
    __shared__ float s2[32][33];
    int bb = b - 256;
    int sd = bb / 48, bx = bb % 48;
    int ktile = bx & 3, rtile = bx >> 2;
    int x = t & 31, y = t >> 5;
    size_t base = (size_t)sd * G3 * DIM;
    #pragma unroll
    for (int j = 0; j < 4; j++) {
        int r = rtile * 32 + y * 4 + j;
        s1[y * 4 + j][x] = Wih[base + (size_t)r * DIM + ktile * 32 + x];
        s2[y * 4 + j][x] = Whh[base + (size_t)r * DIM + ktile * 32 + x];
    }
    __syncthreads();
    size_t obase = (size_t)sd * DIM * G3;
    #pragma unroll
    for (int j = 0; j < 4; j++) {
        int k = ktile * 32 + y * 4 + j;
        g_WihT[obase + (size_t)k * G3 + rtile * 32 + x] = s1[x][y * 4 + j];
        g_WhhT[obase + (size_t)k * G3 + rtile * 32 + x] = s2[x][y * 4 + j];
    }
}

// ---------------- kernel 2: Gi precompute + pair ranking (y==6) ----------------
__global__ __launch_bounds__(384) void k_gi(const float* __restrict__ bih,
                                            const float* __restrict__ anchors)
{
    int t = threadIdx.x;
    if (blockIdx.y == 6) {
        if (blockIdx.x != 0) return;
        __shared__ float tps[N_NODES];
        __shared__ int lens[NA];
        __shared__ int plen[96];
        for (int i = t; i < N_NODES; i += 384) tps[i] = g_tpos[i];
        __syncthreads();
        if (t < NA) {
            float stt = anchors[2 * t], enn = anchors[2 * t + 1];
            int c = 0;
            for (int n = 0; n < N_NODES; n++)
                c += (tps[n] >= stt && tps[n] <= enn) ? 1 : 0;
            lens[t] = c;
        }
        __syncthreads();
        if (t < NA) {
            int s = t >> 6, base = s * 64;
            int L = lens[t];
            int r = 0;
            for (int j = 0; j < 64; j++) {
                int Lj = lens[base + j];
                if (Lj > L || (Lj == L && base + j < t)) r++;
            }
            g_pairs[s * 32 + (r >> 1)][r & 1] = t;
            if ((r & 1) == 0) plen[s * 32 + (r >> 1)] = L;
        }
        __syncthreads();
        if (t < 96) {
            int L = plen[t];
            int g = 0;
            for (int j = 0; j < 96; j++) {
                int Lj = plen[j];
                if (Lj > L || (Lj == L && j < t)) g++;
            }
            g_order[g] = t;
        }
        return;
    }

    int sd = blockIdx.y, chunk = blockIdx.x;
    __shared__ __align__(16) float sx[16 * DIM];
    const float4* src = (const float4*)(g_x + (size_t)chunk * 16 * DIM);
    for (int i = t; i < 16 * DIM / 4; i += 384) ((float4*)sx)[i] = src[i];

    const float* wt = g_WihT + (size_t)sd * DIM * G3 + t;
    ULL w[64];
    #pragma unroll
    for (int k = 0; k < 64; k++) {
        float w0 = wt[(size_t)(2 * k) * G3];
        float w1 = wt[(size_t)(2 * k + 1) * G3];
        asm("mov.b64 %0,{%1,%2};" : "=l"(w[k]) : "f"(w0), "f"(w1));
    }
    float b = bih[sd * G3 + t];
    unsigned xb;
    asm("{.reg .u64 t0; cvta.to.shared.u64 t0,%1; cvt.u32.u64 %0,t0;}" : "=r"(xb) : "l"((float*)sx));
    __syncthreads();

    float* outp = g_Gi + ((size_t)sd * N_NODES + chunk * 16) * G3 + t;
    #pragma unroll 2
    for (int n = 0; n < 16; n++) {
        ULL acA = 0ull, acB = 0ull;
        unsigned base = xb + n * 512;
        #pragma unroll
        for (int i = 0; i < 16; i++) {
            ULL p0, p1, p2, p3;
            asm volatile("ld.shared.v2.b64 {%0,%1},[%2];" : "=l"(p0), "=l"(p1) : "r"(base + i * 32));
            asm volatile("ld.shared.v2.b64 {%0,%1},[%2];" : "=l"(p2), "=l"(p3) : "r"(base + i * 32 + 16));
            asm("fma.rn.f32x2 %0,%1,%2,%0;" : "+l"(acA) : "l"(w[4 * i])     , "l"(p0));
            asm("fma.rn.f32x2 %0,%1,%2,%0;" : "+l"(acB) : "l"(w[4 * i + 1]) , "l"(p1));
            asm("fma.rn.f32x2 %0,%1,%2,%0;" : "+l"(acA) : "l"(w[4 * i + 2]) , "l"(p2));
            asm("fma.rn.f32x2 %0,%1,%2,%0;" : "+l"(acB) : "l"(w[4 * i + 3]) , "l"(p3));
        }
        float a0, a1, b0, b1;
        asm("mov.b64 {%0,%1},%2;" : "=f"(a0), "=f"(a1) : "l"(acA));
        asm("mov.b64 {%0,%1},%2;" : "=f"(b0), "=f"(b1) : "l"(acB));
        outp[(size_t)n * G3] = ((a0 + a1) + (b0 + b1)) + b;
    }
}

// ---------------- kernel 3: GRU, 2 anchors/block, phase-pipelined (gates ∥ other anchor's dot) ----------------
__global__ __launch_bounds__(384, 1) void k_gru(const float* __restrict__ anchors,
                                                const float* __restrict__ bhh,
                                                const float* __restrict__ aWih,
                                                const float* __restrict__ aWhh,
                                                const float* __restrict__ abih,
                                                const float* __restrict__ abhh)
{
    int t = threadIdx.x;
    __shared__ int sh_task[4];
    __shared__ __align__(16) float sh_h[2][DIM];     // hA, hB contiguous (B at +512B)
    __shared__ float ghA[G3];
    __shared__ float ghB[G3];
    __shared__ unsigned short idxAB[2][N_NODES];
    __shared__ int sh_len[2];
    __shared__ float sh_abh[2];
    __shared__ float aw[12];

    if (t == 0) {
        int pr = g_order[blockIdx.x >> 1];
        sh_task[0] = g_pairs[pr][0];
        sh_task[1] = g_pairs[pr][1];
        sh_task[2] = pr >> 5;
        sh_task[3] = blockIdx.x & 1;
    }
    __syncthreads();
    int aA = sh_task[0], aB = sh_task[1], s_ = sh_task[2], dir = sh_task[3];
    int sd = s_ * 2 + dir;

    int wid = t >> 5, lane = t & 31;
    if (wid < 2) {
        int aa = wid ? aB : aA;
        float stt = anchors[2 * aa], enn = anchors[2 * aa + 1];
        unsigned short* ix = idxAB[wid];
        int off = 0;
        for (int base = 0; base < N_NODES; base += 32) {
            int n = base + lane;
            float tp = g_tpos[n];
            bool m = (tp >= stt) && (tp <= enn);
            unsigned bal = __ballot_sync(0xffffffffu, m);
            if (m) ix[off + __popc(bal & ((1u << lane) - 1u))] = (unsigned short)n;
            off += __popc(bal);
        }
        if (dir) {
            for (int i = lane; i < (off >> 1); i += 32) {
                unsigned short tmp = ix[i];
                ix[i] = ix[off - 1 - i];
                ix[off - 1 - i] = tmp;
            }
        }
        if (lane == 0) { sh_len[wid] = off; sh_abh[wid] = 0.f; }
    }
    if (t < DIM) { sh_h[0][t] = 0.f; sh_h[1][t] = 0.f; }
    {
        int base = sd * 3;
        if (t >= 160 && t < 163)  aw[t - 160]      = aWih[base + t - 160];
        if (t >= 163 && t < 166)  aw[3 + t - 163]  = aWhh[base + t - 163];
        if (t >= 166 && t < 169)  aw[6 + t - 166]  = abih[base + t - 166];
        if (t >= 169 && t < 172)  aw[9 + t - 169]  = abhh[base + t - 169];
    }

    // Whh row t -> registers (64 f32x2-packed k-pairs, coalesced from WhhT)
    const float* wt = g_WhhT + (size_t)sd * DIM * G3 + t;
    ULL w[64];
    #pragma unroll
    for (int k = 0; k < 64; k++) {
        float w0 = wt[(size_t)(2 * k) * G3];
        float w1 = wt[(size_t)(2 * k + 1) * G3];
        asm("mov.b64 %0,{%1,%2};" : "=l"(w[k]) : "f"(w0), "f"(w1));
    }
    float bh = bhh[sd * G3 + t];

    unsigned hb;
    asm("{.reg .u64 t0; cvta.to.shared.u64 t0,%1; cvt.u32.u64 %0,t0;}" : "=r"(hb) : "l"(&sh_h[0][0]));
    // prologue: h=0 -> gh(0) for A is just the bias
    ghA[t] = bh;
    __syncthreads();

    int lenA = sh_len[0], lenB = sh_len[1];
    int L = lenA > lenB ? lenA : lenB;
    const float* Gi = g_Gi + (size_t)sd * N_NODES * G3;

    bool gater = (t < 128);          // gate threads handle BOTH anchors (alternating phases)
    int tt = t & 127;

    // preload gate inputs for step 0, both anchors
    float cA0 = 0.f, cA1 = 0.f, cA2 = 0.f;
    float cB0 = 0.f, cB1 = 0.f, cB2 = 0.f;
    if (gater) {
        if (lenA > 0) {
            const float* gp = Gi + (size_t)idxAB[0][0] * G3;
            cA0 = gp[tt]; cA1 = gp[DIM + tt]; cA2 = gp[2 * DIM + tt];
        }
        if (lenB > 0) {
            const float* gp = Gi + (size_t)idxAB[1][0] * G3;
            cB0 = gp[tt]; cB1 = gp[DIM + tt]; cB2 = gp[2 * DIM + tt];
        }
    }
    float abA = 0.f, abB = 0.f;
    if (t == 128) {
        if (lenA > 0) abA = g_abn[idxAB[0][0]];
        if (lenB > 0) abB = g_abn[idxAB[1][0]];
    }

    for (int s = 0; s < L; s++) {
        // ---------- EVEN phase: gates-A(s)  ∥  dot-B(s) ----------
        {
            // prefetch cA(s+1)
            float nA0 = 0.f, nA1 = 0.f, nA2 = 0.f, abAn = 0.f;
            int sn = s + 1;
            if (gater && sn < lenA) {
                const float* gp = Gi + (size_t)idxAB[0][sn] * G3;
                nA0 = gp[tt]; nA1 = gp[DIM + tt]; nA2 = gp[2 * DIM + tt];
            }
            if (t == 128 && sn < lenA) abAn = g_abn[idxAB[0][sn]];

            // gates-A(s): ghA completed last phase
            if (gater && s < lenA) {
                float r  = sigf(cA0 + ghA[tt]);
                float z  = sigf(cA1 + ghA[DIM + tt]);
                float nn = tanhfast(cA2 + r * ghA[2 * DIM + tt]);
                sh_h[0][tt] = (1.f - z) * nn + z * sh_h[0][tt];
            }
            if (t == 128 && s < lenA) {
                float h = sh_abh[0];
                float r  = sigf(aw[0] * abA + aw[6] + aw[3] * h + aw[9]);
                float z  = sigf(aw[1] * abA + aw[7] + aw[4] * h + aw[10]);
                float nn = tanhfast(aw[2] * abA + aw[8] + r * (aw[5] * h + aw[11]));
                sh_abh[0] = (1.f - z) * nn + z * h;
            }

            // dot-B(s): all threads, reads hB (stable this phase)
            ULL a0c = 0ull, a1c = 0ull, a2c = 0ull, a3c = 0ull;
            #pragma unroll
            for (int i = 0; i < 16; i++) {
                ULL x0, x1, x2, x3;
                asm volatile("ld.shared.v2.b64 {%0,%1},[%2];" : "=l"(x0), "=l"(x1) : "r"(hb + 512 + i * 32));
                asm volatile("ld.shared.v2.b64 {%0,%1},[%2];" : "=l"(x2), "=l"(x3) : "r"(hb + 512 + i * 32 + 16));
                asm("fma.rn.f32x2 %0,%1,%2,%0;" : "+l"(a0c) : "l"(w[4 * i])     , "l"(x0));
                asm("fma.rn.f32x2 %0,%1,%2,%0;" : "+l"(a1c) : "l"(w[4 * i + 1]) , "l"(x1));
                asm("fma.rn.f32x2 %0,%1,%2,%0;" : "+l"(a2c) : "l"(w[4 * i + 2]) , "l"(x2));
                asm("fma.rn.f32x2 %0,%1,%2,%0;" : "+l"(a3c) : "l"(w[4 * i + 3]) , "l"(x3));
            }
            float p0, p1, p2, p3, p4, p5, p6, p7;
            asm("mov.b64 {%0,%1},%2;" : "=f"(p0), "=f"(p1) : "l"(a0c));
            asm("mov.b64 {%0,%1},%2;" : "=f"(p2), "=f"(p3) : "l"(a1c));
            asm("mov.b64 {%0,%1},%2;" : "=f"(p4), "=f"(p5) : "l"(a2c));
            asm("mov.b64 {%0,%1},%2;" : "=f"(p6), "=f"(p7) : "l"(a3c));
            ghB[t] = (((p0 + p1) + (p2 + p3)) + ((p4 + p5) + (p6 + p7))) + bh;

            cA0 = nA0; cA1 = nA1; cA2 = nA2; abA = abAn;
        }
        __syncthreads();

        // ---------- ODD phase: gates-B(s)  ∥  dot-A(s+1) ----------
        {
            // prefetch cB(s+1)
            float nB0 = 0.f, nB1 = 0.f, nB2 = 0.f, abBn = 0.f;
            int sn = s + 1;
            if (gater && sn < lenB) {
                const float* gp = Gi + (size_t)idxAB[1][sn] * G3;
                nB0 = gp[tt]; nB1 = gp[DIM + tt]; nB2 = gp[2 * DIM + tt];
            }
            if (t == 128 && sn < lenB) abBn = g_abn[idxAB[1][sn]];

            // gates-B(s): ghB completed in even phase
            if (gater && s < lenB) {
                float r  = sigf(cB0 + ghB[tt]);
                float z  = sigf(cB1 + ghB[DIM + tt]);
                float nn = tanhfast(cB2 + r * ghB[2 * DIM + tt]);
                sh_h[1][tt] = (1.f - z) * nn + z * sh_h[1][tt];
            }
            if (t == 128 && s < lenB) {
                float h = sh_abh[1];
                float r  = sigf(aw[0] * abB + aw[6] + aw[3] * h + aw[9]);
                float z  = sigf(aw[1] * abB + aw[7] + aw[4] * h + aw[10]);
                float nn = tanhfast(aw[2] * abB + aw[8] + r * (aw[5] * h + aw[11]));
                sh_abh[1] = (1.f - z) * nn + z * h;
            }

            // dot-A(s+1): reads hA updated by gates-A(s) last phase
            ULL a0c = 0ull, a1c = 0ull, a2c = 0ull, a3c = 0ull;
            #pragma unroll
            for (int i = 0; i < 16; i++) {
                ULL x0, x1, x2, x3;
                asm volatile("ld.shared.v2.b64 {%0,%1},[%2];" : "=l"(x0), "=l"(x1) : "r"(hb + i * 32));
                asm volatile("ld.shared.v2.b64 {%0,%1},[%2];" : "=l"(x2), "=l"(x3) : "r"(hb + i * 32 + 16));
                asm("fma.rn.f32x2 %0,%1,%2,%0;" : "+l"(a0c) : "l"(w[4 * i])     , "l"(x0));
                asm("fma.rn.f32x2 %0,%1,%2,%0;" : "+l"(a1c) : "l"(w[4 * i + 1]) , "l"(x1));
                asm("fma.rn.f32x2 %0,%1,%2,%0;" : "+l"(a2c) : "l"(w[4 * i + 2]) , "l"(x2));
                asm("fma.rn.f32x2 %0,%1,%2,%0;" : "+l"(a3c) : "l"(w[4 * i + 3]) , "l"(x3));
            }
            float p0, p1, p2, p3, p4, p5, p6, p7;
            asm("mov.b64 {%0,%1},%2;" : "=f"(p0), "=f"(p1) : "l"(a0c));
            asm("mov.b64 {%0,%1},%2;" : "=f"(p2), "=f"(p3) : "l"(a1c));
            asm("mov.b64 {%0,%1},%2;" : "=f"(p4), "=f"(p5) : "l"(a2c));
            asm("mov.b64 {%0,%1},%2;" : "=f"(p6), "=f"(p7) : "l"(a3c));
            ghA[t] = (((p0 + p1) + (p2 + p3)) + ((p4 + p5) + (p6 + p7))) + bh;

            cB0 = nB0; cB1 = nB1; cB2 = nB2; abB = abBn;
        }
        __syncthreads();
    }

    if (t < DIM) {
        g_hout[((size_t)aA * 2 + dir) * DIM + t] = sh_h[0][t];
        g_hout[((size_t)aB * 2 + dir) * DIM + t] = sh_h[1][t];
    }
    if (t == 128) {
        g_abnout[aA * 2 + dir] = sh_abh[0];
        g_abnout[aB * 2 + dir] = sh_abh[1];
    }
}

// ---------------- kernel 4: MLP head (r9 best variant) ----------------
__global__ __launch_bounds__(256) void k_head(const float* __restrict__ anchors,
                                              const float* __restrict__ al_p,
                                              const float* __restrict__ W1, const float* __restrict__ b1,
                                              const float* __restrict__ W2, const float* __restrict__ b2,
                                              const float* __restrict__ W3, const float* __restrict__ b3,
                                              const float* __restrict__ start_w,
                                              const float* __restrict__ end_w,
                                              float* __restrict__ out)
{
    int a = blockIdx.x;
    int s = a >> 6;
    int t = threadIdx.x;
    const int FIN = 2 * DIM + 3;   // 259
    const int FOUT = 47;

    __shared__ float sf[FIN + 1];
    __shared__ float h1[256];
    __shared__ float h2[256];
    __shared__ float o[FOUT + 1];
    __shared__ float soeo[2];

    float al = al_p[0];
    if (t < DIM) {
        sf[t]       = g_hout[((size_t)a * 2 + 0) * DIM + t];
        sf[DIM + t] = g_hout[((size_t)a * 2 + 1) * DIM + t];
    }
    if (t == 0) {
        sf[256] = 0.5f * (g_abnout[a * 2] + g_abnout[a * 2 + 1]);
        float stt = anchors[a * 2], enn = anchors[a * 2 + 1];
        sf[257] = (stt + enn) * 0.5f / al;
        sf[258] = (enn - stt) / al;
    }
    __syncthreads();

    {
        const float* W = W1 + (size_t)s * FIN * 256 + t;
        float acc[8];
        #pragma unroll
        for (int q = 0; q < 8; q++) acc[q] = 0.f;
        float wreg[64];
        #pragma unroll
        for (int p = 0; p < 4; p++) {
            int i0 = p * 64;
            #pragma unroll
            for (int j = 0; j < 64; j++) wreg[j] = W[(size_t)(i0 + j) * 256];
            #pragma unroll
            for (int j = 0; j < 64; j++) acc[j & 7] += wreg[j] * sf[i0 + j];
        }
        acc[0] += W[(size_t)256 * 256] * sf[256];
        acc[1] += W[(size_t)257 * 256] * sf[257];
        acc[2] += W[(size_t)258 * 256] * sf[258];
        float r = (((acc[0] + acc[1]) + (acc[2] + acc[3])) + ((acc[4] + acc[5]) + (acc[6] + acc[7])))
                  + b1[s * 256 + t];
        h1[t] = fmaxf(r, 0.f);
    }
    __syncthreads();

    {
        const float* W = W2 + (size_t)s * 256 * 256 + t;
        float acc[8];
        #pragma unroll
        for (int q = 0; q < 8; q++) acc[q] = 0.f;
        float wreg[64];
        #pragma unroll
        for (int p = 0; p < 4; p++) {
            int i0 = p * 64;
            #pragma unroll
            for (int j = 0; j < 64; j++) wreg[j] = W[(size_t)(i0 + j) * 256];
            #pragma unroll
            for (int j = 0; j < 64; j++) acc[j & 7] += wreg[j] * h1[i0 + j];
        }
        float r = (((acc[0] + acc[1]) + (acc[2] + acc[3])) + ((acc[4] + acc[5]) + (acc[6] + acc[7])))
                  + b2[s * 256 + t];
        h2[t] = fmaxf(r, 0.f);
    }
    __syncthreads();

    if (t < FOUT) {
        const float* W = W3 + (size_t)s * 256 * FOUT + t;
        float acc[8];
        #pragma unroll
        for (int q = 0; q < 8; q++) acc[q] = 0.f;
        float wreg[64];
        #pragma unroll
        for (int p = 0; p < 4; p++) {
            int i0 = p * 64;
            #pragma unroll
            for (int j = 0; j < 64; j++) wreg[j] = W[(size_t)(i0 + j) * FOUT];
            #pragma unroll
            for (int j = 0; j < 64; j++) acc[j & 7] += wreg[j] * h2[i0 + j];
        }
        o[t] = (((acc[0] + acc[1]) + (acc[2] + acc[3])) + ((acc[4] + acc[5]) + (acc[6] + acc[7])))
               + b3[s * FOUT + t];
    }
    __syncthreads();

    if (t < 2) {
        const float* wv = (t == 0) ? (start_w + s * 21) : (end_w + s * 21);
        const float* ov = o + t * 21;
        float m = -1e30f;
        for (int j = 0; j < 21; j++) m = fmaxf(m, ov[j]);
        float den = 0.f, num = 0.f;
        for (int j = 0; j < 21; j++) { float e = __expf(ov[j] - m); den += e; num += e * wv[j]; }
        soeo[t] = num / den;
    }
    __syncthreads();

    if (t == 0) {
        float stt = anchors[a * 2], enn = anchors[a * 2 + 1];
        out[a * 2]      = fminf(fmaxf(stt + soeo[0], 0.f), al);
        out[a * 2 + 1]  = fminf(fmaxf(enn + soeo[1], 0.f), al);
        out[2 * NA + a] = o[42];
    }
    if (t < 4) out[3 * NA + a * 4 + t] = o[43 + t];
}

// ---------------- launcher ----------------
extern "C" void kernel_launch(void* const* d_in, const int* in_sizes, int n_in,
                              void* d_out, int out_size)
{
    const float* emb   = (const float*)d_in[0];
    const float* tp    = (const float*)d_in[1];
    const float* pred  = (const float*)d_in[2];
    const float* al_p  = (const float*)d_in[3];
    const float* anc   = (const float*)d_in[4];
    const float* kern  = (const float*)d_in[5];
    const float* fWih  = (const float*)d_in[6];
    const float* fWhh  = (const float*)d_in[7];
    const float* fbih  = (const float*)d_in[8];
    const float* fbhh  = (const float*)d_in[9];
    const float* aWih  = (const float*)d_in[10];
    const float* aWhh  = (const float*)d_in[11];
    const float* abih  = (const float*)d_in[12];
    const float* abhh  = (const float*)d_in[13];
    const float* sw    = (const float*)d_in[14];
    const float* ew    = (const float*)d_in[15];
    const float* W1    = (const float*)d_in[16];
    const float* b1    = (const float*)d_in[17];
    const float* W2    = (const float*)d_in[18];
    const float* b2    = (const float*)d_in[19];
    const float* W3    = (const float*)d_in[20];
    const float* b3    = (const float*)d_in[21];
    float* outp = (float*)d_out;

    k_pre_tr<<<544, 256>>>(emb, tp, pred, al_p, kern, fWih, fWhh);
    k_gi<<<dim3(32, 7), 384>>>(fbih, anc);
    k_gru<<<NA, 384>>>(anc, fbhh, aWih, aWhh, abih, abhh);
    k_head<<<NA, 256>>>(anc, al_p, W1, b1, W2, b2, W3, b3, sw, ew, outp);
}

// round 15
// speedup vs baseline: 1.0317x; 1.0317x over previous
#include <cuda_runtime.h>
#include <math.h>

#define N_NODES 512
#define DIM 128
#define NA 192          // total anchors
#define G3 384          // 3*DIM
typedef unsigned long long ULL;

// ---------------- scratch (no allocations allowed) ----------------
__device__ float g_x[N_NODES * DIM];
__device__ float g_abn[N_NODES];
__device__ float g_tpos[N_NODES];
__device__ float g_Gi[6 * N_NODES * G3];
__device__ float g_hout[NA * 2 * DIM];
__device__ float g_abnout[NA * 2];
__device__ float g_WihT[6 * DIM * G3];   // [sd][k][row]
__device__ float g_WhhT[6 * DIM * G3];   // [sd][k][row]
__device__ int   g_pairs[96][2];         // [scale*32+pair][2], len-matched within scale
__device__ int   g_order[96];            // pair schedule, len desc
__device__ int   g_done[NA];             // per-anchor completion count (0..2)

__device__ __forceinline__ float sigf(float x) { return 1.f / (1.f + __expf(-x)); }
__device__ __forceinline__ float tanhfast(float x) { return 2.f / (1.f + __expf(-2.f * x)) - 1.f; }

// ---------------- kernel 1 (fused): preprocess + GRU weight transpose ----------------
__global__ void k_pre_tr(const float* __restrict__ emb, const float* __restrict__ tp,
                         const float* __restrict__ pred, const float* __restrict__ al_p,
                         const float* __restrict__ kern,
                         const float* __restrict__ Wih, const float* __restrict__ Whh)
{
    int b = blockIdx.x;
    int t = threadIdx.x;
    if (b < 256) {
        int tid = b * 256 + t;
        if (tid < NA) g_done[tid] = 0;            // reset fusion counters every replay
        if (tid < N_NODES * DIM) {
            int n = tid >> 7, d = tid & 127;
            float freq = (10.f / 127.f) * (float)d;
            g_x[tid] = emb[tid] + 0.05f * sinf(tp[n] * freq);
        }
        if (tid < N_NODES) {
            int n = tid;
            float kv[5];
            #pragma unroll
            for (int k = 0; k < 5; k++) kv[k] = kern[k];
            float sv[5];
            #pragma unroll
            for (int c = 0; c < 5; c++) {
                float acc = 0.f;
                #pragma unroll
                for (int k = 0; k < 5; k++) {
                    int nn = n + k - 2;
                    if (nn >= 0 && nn < N_NODES) acc += kv[k] * pred[nn * 5 + c];
                }
                sv[c] = acc;
            }
            float m = sv[0];
            #pragma unroll
            for (int c = 1; c < 5; c++) m = fmaxf(m, sv[c]);
            float den = 0.f;
            #pragma unroll
            for (int c = 0; c < 5; c++) den += __expf(sv[c] - m);
            g_abn[n] = __expf(sv[0] - m) / den;
            g_tpos[n] = tp[n] * al_p[0];
        }
        return;
    }
    // GRU weight transpose (tiled, coalesced both sides)
    __shared__ float s1[32][33];
    __shared__ float s2[32][33];
    int bb = b - 256;
    int sd = bb / 48, bx = bb % 48;
    int ktile = bx & 3, rtile = bx >> 2;
    int x = t & 31, y = t >> 5;
    size_t base = (size_t)sd * G3 * DIM;
    #pragma unroll
    for (int j = 0; j < 4; j++) {
        int r = rtile * 32 + y * 4 + j;
        s1[y * 4 + j][x] = Wih[base + (size_t)r * DIM + ktile * 32 + x];
        s2[y * 4 + j][x] = Whh[base + (size_t)r * DIM + ktile * 32 + x];
    }
    __syncthreads();
    size_t obase = (size_t)sd * DIM * G3;
    #pragma unroll
    for (int j = 0; j < 4; j++) {
        int k = ktile * 32 + y * 4 + j;
        g_WihT[obase + (size_t)k * G3 + rtile * 32 + x] = s1[x][y * 4 + j];
        g_WhhT[obase + (size_t)k * G3 + rtile * 32 + x] = s2[x][y * 4 + j];
    }
}

// ---------------- kernel 2: Gi precompute + pair ranking (y==6) ----------------
__global__ __launch_bounds__(384) void k_gi(const float* __restrict__ bih,
                                            const float* __restrict__ anchors)
{
    int t = threadIdx.x;
    if (blockIdx.y == 6) {
        if (blockIdx.x != 0) return;
        __shared__ float tps[N_NODES];
        __shared__ int lens[NA];
        __shared__ int plen[96];
        for (int i = t; i < N_NODES; i += 384) tps[i] = g_tpos[i];
        __syncthreads();
        if (t < NA) {
            float stt = anchors[2 * t], enn = anchors[2 * t + 1];
            int c = 0;
            for (int n = 0; n < N_NODES; n++)
                c += (tps[n] >= stt && tps[n] <= enn) ? 1 : 0;
            lens[t] = c;
        }
        __syncthreads();
        if (t < NA) {
            int s = t >> 6, base = s * 64;
            int L = lens[t];
            int r = 0;
            for (int j = 0; j < 64; j++) {
                int Lj = lens[base + j];
                if (Lj > L || (Lj == L && base + j < t)) r++;
            }
            g_pairs[s * 32 + (r >> 1)][r & 1] = t;
            if ((r & 1) == 0) plen[s * 32 + (r >> 1)] = L;
        }
        __syncthreads();
        if (t < 96) {
            int L = plen[t];
            int g = 0;
            for (int j = 0; j < 96; j++) {
                int Lj = plen[j];
                if (Lj > L || (Lj == L && j < t)) g++;
            }
            g_order[g] = t;
        }
        return;
    }

    int sd = blockIdx.y, chunk = blockIdx.x;
    __shared__ __align__(16) float sx[16 * DIM];
    const float4* src = (const float4*)(g_x + (size_t)chunk * 16 * DIM);
    for (int i = t; i < 16 * DIM / 4; i += 384) ((float4*)sx)[i] = src[i];

    const float* wt = g_WihT + (size_t)sd * DIM * G3 + t;
    ULL w[64];
    #pragma unroll
    for (int k = 0; k < 64; k++) {
        float w0 = wt[(size_t)(2 * k) * G3];
        float w1 = wt[(size_t)(2 * k + 1) * G3];
        asm("mov.b64 %0,{%1,%2};" : "=l"(w[k]) : "f"(w0), "f"(w1));
    }
    float b = bih[sd * G3 + t];
    unsigned xb;
    asm("{.reg .u64 t0; cvta.to.shared.u64 t0,%1; cvt.u32.u64 %0,t0;}" : "=r"(xb) : "l"((float*)sx));
    __syncthreads();

    float* outp = g_Gi + ((size_t)sd * N_NODES + chunk * 16) * G3 + t;
    #pragma unroll 2
    for (int n = 0; n < 16; n++) {
        ULL acA = 0ull, acB = 0ull;
        unsigned base = xb + n * 512;
        #pragma unroll
        for (int i = 0; i < 16; i++) {
            ULL p0, p1, p2, p3;
            asm volatile("ld.shared.v2.b64 {%0,%1},[%2];" : "=l"(p0), "=l"(p1) : "r"(base + i * 32));
            asm volatile("ld.shared.v2.b64 {%0,%1},[%2];" : "=l"(p2), "=l"(p3) : "r"(base + i * 32 + 16));
            asm("fma.rn.f32x2 %0,%1,%2,%0;" : "+l"(acA) : "l"(w[4 * i])     , "l"(p0));
            asm("fma.rn.f32x2 %0,%1,%2,%0;" : "+l"(acB) : "l"(w[4 * i + 1]) , "l"(p1));
            asm("fma.rn.f32x2 %0,%1,%2,%0;" : "+l"(acA) : "l"(w[4 * i + 2]) , "l"(p2));
            asm("fma.rn.f32x2 %0,%1,%2,%0;" : "+l"(acB) : "l"(w[4 * i + 3]) , "l"(p3));
        }
        float a0, a1, b0, b1;
        asm("mov.b64 {%0,%1},%2;" : "=f"(a0), "=f"(a1) : "l"(acA));
        asm("mov.b64 {%0,%1},%2;" : "=f"(b0), "=f"(b1) : "l"(acB));
        outp[(size_t)n * G3] = ((a0 + a1) + (b0 + b1)) + b;
    }
}

// ---------------- fused MLP head (runs inside k_gru tail; 384 threads, 256 active) ----------------
__device__ __noinline__ void run_head(int a,
                                      const float* __restrict__ anchors, float al,
                                      const float* __restrict__ W1, const float* __restrict__ b1,
                                      const float* __restrict__ W2, const float* __restrict__ b2,
                                      const float* __restrict__ W3, const float* __restrict__ b3,
                                      const float* __restrict__ start_w,
                                      const float* __restrict__ end_w,
                                      float* __restrict__ out)
{
    int s = a >> 6;
    int t = threadIdx.x;
    const int FIN = 2 * DIM + 3;   // 259
    const int FOUT = 47;

    __shared__ float sf[FIN + 1];
    __shared__ float h1[256];
    __shared__ float h2[256];
    __shared__ float o[FOUT + 1];
    __shared__ float soeo[2];

    if (t < DIM) {
        sf[t]       = g_hout[((size_t)a * 2 + 0) * DIM + t];
        sf[DIM + t] = g_hout[((size_t)a * 2 + 1) * DIM + t];
    }
    if (t == 0) {
        sf[256] = 0.5f * (g_abnout[a * 2] + g_abnout[a * 2 + 1]);
        float stt = anchors[a * 2], enn = anchors[a * 2 + 1];
        sf[257] = (stt + enn) * 0.5f / al;
        sf[258] = (enn - stt) / al;
    }
    __syncthreads();

    if (t < 256) {
        const float* W = W1 + (size_t)s * FIN * 256 + t;
        float acc[8];
        #pragma unroll
        for (int q = 0; q < 8; q++) acc[q] = 0.f;
        float wreg[32];
        #pragma unroll
        for (int p = 0; p < 8; p++) {
            int i0 = p * 32;
            #pragma unroll
            for (int j = 0; j < 32; j++) wreg[j] = W[(size_t)(i0 + j) * 256];
            #pragma unroll
            for (int j = 0; j < 32; j++) acc[j & 7] += wreg[j] * sf[i0 + j];
        }
        acc[0] += W[(size_t)256 * 256] * sf[256];
        acc[1] += W[(size_t)257 * 256] * sf[257];
        acc[2] += W[(size_t)258 * 256] * sf[258];
        float r = (((acc[0] + acc[1]) + (acc[2] + acc[3])) + ((acc[4] + acc[5]) + (acc[6] + acc[7])))
                  + b1[s * 256 + t];
        h1[t] = fmaxf(r, 0.f);
    }
    __syncthreads();

    if (t < 256) {
        const float* W = W2 + (size_t)s * 256 * 256 + t;
        float acc[8];
        #pragma unroll
        for (int q = 0; q < 8; q++) acc[q] = 0.f;
        float wreg[32];
        #pragma unroll
        for (int p = 0; p < 8; p++) {
            int i0 = p * 32;
            #pragma unroll
            for (int j = 0; j < 32; j++) wreg[j] = W[(size_t)(i0 + j) * 256];
            #pragma unroll
            for (int j = 0; j < 32; j++) acc[j & 7] += wreg[j] * h1[i0 + j];
        }
        float r = (((acc[0] + acc[1]) + (acc[2] + acc[3])) + ((acc[4] + acc[5]) + (acc[6] + acc[7])))
                  + b2[s * 256 + t];
        h2[t] = fmaxf(r, 0.f);
    }
    __syncthreads();

    if (t < FOUT) {
        const float* W = W3 + (size_t)s * 256 * FOUT + t;
        float acc[8];
        #pragma unroll
        for (int q = 0; q < 8; q++) acc[q] = 0.f;
        float wreg[32];
        #pragma unroll
        for (int p = 0; p < 8; p++) {
            int i0 = p * 32;
            #pragma unroll
            for (int j = 0; j < 32; j++) wreg[j] = W[(size_t)(i0 + j) * FOUT];
            #pragma unroll
            for (int j = 0; j < 32; j++) acc[j & 7] += wreg[j] * h2[i0 + j];
        }
        o[t] = (((acc[0] + acc[1]) + (acc[2] + acc[3])) + ((acc[4] + acc[5]) + (acc[6] + acc[7])))
               + b3[s * FOUT + t];
    }
    __syncthreads();

    if (t < 2) {
        const float* wv = (t == 0) ? (start_w + s * 21) : (end_w + s * 21);
        const float* ov = o + t * 21;
        float m = -1e30f;
        for (int j = 0; j < 21; j++) m = fmaxf(m, ov[j]);
        float den = 0.f, num = 0.f;
        for (int j = 0; j < 21; j++) { float e = __expf(ov[j] - m); den += e; num += e * wv[j]; }
        soeo[t] = num / den;
    }
    __syncthreads();

    if (t == 0) {
        float stt = anchors[a * 2], enn = anchors[a * 2 + 1];
        out[a * 2]      = fminf(fmaxf(stt + soeo[0], 0.f), al);
        out[a * 2 + 1]  = fminf(fmaxf(enn + soeo[1], 0.f), al);
        out[2 * NA + a] = o[42];
    }
    if (t < 4) out[3 * NA + a * 4 + t] = o[43 + t];
    __syncthreads();
}

// ---------------- kernel 3: GRU (r9 core) + fused head epilogue ----------------
__global__ __launch_bounds__(384, 1) void k_gru(const float* __restrict__ anchors,
                                                const float* __restrict__ bhh,
                                                const float* __restrict__ aWih,
                                                const float* __restrict__ aWhh,
                                                const float* __restrict__ abih,
                                                const float* __restrict__ abhh,
                                                const float* __restrict__ al_p,
                                                const float* __restrict__ W1, const float* __restrict__ b1,
                                                const float* __restrict__ W2, const float* __restrict__ b2,
                                                const float* __restrict__ W3, const float* __restrict__ b3,
                                                const float* __restrict__ start_w,
                                                const float* __restrict__ end_w,
                                                float* __restrict__ out)
{
    int t = threadIdx.x;
    __shared__ int sh_task[4];
    __shared__ __align__(16) float sh_h[2][DIM];
    __shared__ float ghA[G3];
    __shared__ float ghB[G3];
    __shared__ unsigned short idxAB[2][N_NODES];
    __shared__ int sh_len[2];
    __shared__ float sh_abh[2];
    __shared__ float aw[12];
    __shared__ int sh_run[2];

    if (t == 0) {
        int pr = g_order[blockIdx.x >> 1];
        sh_task[0] = g_pairs[pr][0];
        sh_task[1] = g_pairs[pr][1];
        sh_task[2] = pr >> 5;
        sh_task[3] = blockIdx.x & 1;
    }
    __syncthreads();
    int aA = sh_task[0], aB = sh_task[1], s = sh_task[2], dir = sh_task[3];
    int sd = s * 2 + dir;

    int wid = t >> 5, lane = t & 31;
    if (wid < 2) {
        int aa = wid ? aB : aA;
        float stt = anchors[2 * aa], enn = anchors[2 * aa + 1];
        unsigned short* ix = idxAB[wid];
        int off = 0;
        for (int base = 0; base < N_NODES; base += 32) {
            int n = base + lane;
            float tp = g_tpos[n];
            bool m = (tp >= stt) && (tp <= enn);
            unsigned bal = __ballot_sync(0xffffffffu, m);
            if (m) ix[off + __popc(bal & ((1u << lane) - 1u))] = (unsigned short)n;
            off += __popc(bal);
        }
        if (dir) {
            for (int i = lane; i < (off >> 1); i += 32) {
                unsigned short tmp = ix[i];
                ix[i] = ix[off - 1 - i];
                ix[off - 1 - i] = tmp;
            }
        }
        if (lane == 0) { sh_len[wid] = off; sh_abh[wid] = 0.f; }
    }
    if (t < DIM) { sh_h[0][t] = 0.f; sh_h[1][t] = 0.f; }
    {
        int base = sd * 3;
        if (t >= 64 && t < 67)  aw[t - 64]      = aWih[base + t - 64];
        if (t >= 67 && t < 70)  aw[3 + t - 67]  = aWhh[base + t - 67];
        if (t >= 70 && t < 73)  aw[6 + t - 70]  = abih[base + t - 70];
        if (t >= 73 && t < 76)  aw[9 + t - 73]  = abhh[base + t - 73];
    }

    const float* wt = g_WhhT + (size_t)sd * DIM * G3 + t;
    ULL w[64];
    #pragma unroll
    for (int k = 0; k < 64; k++) {
        float w0 = wt[(size_t)(2 * k) * G3];
        float w1 = wt[(size_t)(2 * k + 1) * G3];
        asm("mov.b64 %0,{%1,%2};" : "=l"(w[k]) : "f"(w0), "f"(w1));
    }
    float bh = bhh[sd * G3 + t];

    unsigned hb;
    asm("{.reg .u64 t0; cvta.to.shared.u64 t0,%1; cvt.u32.u64 %0,t0;}" : "=r"(hb) : "l"(&sh_h[0][0]));
    __syncthreads();

    int lenA = sh_len[0], lenB = sh_len[1];
    int L = lenA > lenB ? lenA : lenB;
    const float* Gi = g_Gi + (size_t)sd * N_NODES * G3;

    bool roleA = (t < 128);
    bool roleB = (t >= 128 && t < 256);
    int tt = t & 127;
    int mylen = roleA ? lenA : (roleB ? lenB : 0);
    const unsigned short* myidx = roleA ? idxAB[0] : idxAB[1];

    float c0 = 0.f, c1 = 0.f, c2 = 0.f;
    if ((roleA || roleB) && mylen > 0) {
        const float* gp = Gi + (size_t)myidx[0] * G3;
        c0 = gp[tt]; c1 = gp[DIM + tt]; c2 = gp[2 * DIM + tt];
    }
    float abc = 0.f;
    if (t == 256 && lenA > 0) abc = g_abn[idxAB[0][0]];
    if (t == 257 && lenB > 0) abc = g_abn[idxAB[1][0]];

    for (int step = 0; step < L; step++) {
        float n0 = 0.f, n1 = 0.f, n2 = 0.f, abn_next = 0.f;
        int sn = step + 1;
        if ((roleA || roleB) && sn < mylen) {
            const float* gp = Gi + (size_t)myidx[sn] * G3;
            n0 = gp[tt]; n1 = gp[DIM + tt]; n2 = gp[2 * DIM + tt];
        }
        if (t == 256 && sn < lenA) abn_next = g_abn[idxAB[0][sn]];
        if (t == 257 && sn < lenB) abn_next = g_abn[idxAB[1][sn]];

        ULL accA0 = 0ull, accA1 = 0ull, accB0 = 0ull, accB1 = 0ull;
        #pragma unroll
        for (int i = 0; i < 32; i++) {
            ULL a0, a1, b0, b1;
            asm volatile("ld.shared.v2.b64 {%0,%1},[%2];" : "=l"(a0), "=l"(a1) : "r"(hb + i * 16));
            asm volatile("ld.shared.v2.b64 {%0,%1},[%2];" : "=l"(b0), "=l"(b1) : "r"(hb + 512 + i * 16));
            asm("fma.rn.f32x2 %0,%1,%2,%0;" : "+l"(accA0) : "l"(w[2 * i])     , "l"(a0));
            asm("fma.rn.f32x2 %0,%1,%2,%0;" : "+l"(accB0) : "l"(w[2 * i])     , "l"(b0));
            asm("fma.rn.f32x2 %0,%1,%2,%0;" : "+l"(accA1) : "l"(w[2 * i + 1]) , "l"(a1));
            asm("fma.rn.f32x2 %0,%1,%2,%0;" : "+l"(accB1) : "l"(w[2 * i + 1]) , "l"(b1));
        }
        float pa0, pa1, pa2, pa3, pb0, pb1, pb2, pb3;
        asm("mov.b64 {%0,%1},%2;" : "=f"(pa0), "=f"(pa1) : "l"(accA0));
        asm("mov.b64 {%0,%1},%2;" : "=f"(pa2), "=f"(pa3) : "l"(accA1));
        asm("mov.b64 {%0,%1},%2;" : "=f"(pb0), "=f"(pb1) : "l"(accB0));
        asm("mov.b64 {%0,%1},%2;" : "=f"(pb2), "=f"(pb3) : "l"(accB1));
        ghA[t] = ((pa0 + pa1) + (pa2 + pa3)) + bh;
        ghB[t] = ((pb0 + pb1) + (pb2 + pb3)) + bh;
        __syncthreads();

        bool actA = step < lenA, actB = step < lenB;
        if (roleA) {
            if (actA) {
                float r  = sigf(c0 + ghA[tt]);
                float z  = sigf(c1 + ghA[DIM + tt]);
                float nn = tanhfast(c2 + r * ghA[2 * DIM + tt]);
                sh_h[0][tt] = (1.f - z) * nn + z * sh_h[0][tt];
            }
        } else if (roleB) {
            if (actB) {
                float r  = sigf(c0 + ghB[tt]);
                float z  = sigf(c1 + ghB[DIM + tt]);
                float nn = tanhfast(c2 + r * ghB[2 * DIM + tt]);
                sh_h[1][tt] = (1.f - z) * nn + z * sh_h[1][tt];
            }
        } else if (t == 256) {
            if (actA) {
                float h = sh_abh[0];
                float r  = sigf(aw[0] * abc + aw[6] + aw[3] * h + aw[9]);
                float z  = sigf(aw[1] * abc + aw[7] + aw[4] * h + aw[10]);
                float nn = tanhfast(aw[2] * abc + aw[8] + r * (aw[5] * h + aw[11]));
                sh_abh[0] = (1.f - z) * nn + z * h;
            }
        } else if (t == 257) {
            if (actB) {
                float h = sh_abh[1];
                float r  = sigf(aw[0] * abc + aw[6] + aw[3] * h + aw[9]);
                float z  = sigf(aw[1] * abc + aw[7] + aw[4] * h + aw[10]);
                float nn = tanhfast(aw[2] * abc + aw[8] + r * (aw[5] * h + aw[11]));
                sh_abh[1] = (1.f - z) * nn + z * h;
            }
        }
        c0 = n0; c1 = n1; c2 = n2; abc = abn_next;
        __syncthreads();
    }

    if (roleA)      g_hout[((size_t)aA * 2 + dir) * DIM + tt] = sh_h[0][tt];
    else if (roleB) g_hout[((size_t)aB * 2 + dir) * DIM + tt] = sh_h[1][tt];
    else if (t == 256) g_abnout[aA * 2 + dir] = sh_abh[0];
    else if (t == 257) g_abnout[aB * 2 + dir] = sh_abh[1];

    // ---- fused head epilogue: last-finisher per anchor runs its MLP head ----
    __threadfence();                 // publish this block's g_hout/g_abnout writes
    __syncthreads();                 // all writes + fences done before the atomic
    if (t == 0) {
        sh_run[0] = (atomicAdd(&g_done[aA], 1) == 1) ? 1 : 0;
        sh_run[1] = (atomicAdd(&g_done[aB], 1) == 1) ? 1 : 0;
    }
    __syncthreads();
    float al = al_p[0];
    if (sh_run[0]) run_head(aA, anchors, al, W1, b1, W2, b2, W3, b3, start_w, end_w, out);
    if (sh_run[1]) run_head(aB, anchors, al, W1, b1, W2, b2, W3, b3, start_w, end_w, out);
}

// ---------------- launcher ----------------
extern "C" void kernel_launch(void* const* d_in, const int* in_sizes, int n_in,
                              void* d_out, int out_size)
{
    const float* emb   = (const float*)d_in[0];
    const float* tp    = (const float*)d_in[1];
    const float* pred  = (const float*)d_in[2];
    const float* al_p  = (const float*)d_in[3];
    const float* anc   = (const float*)d_in[4];
    const float* kern  = (const float*)d_in[5];
    const float* fWih  = (const float*)d_in[6];
    const float* fWhh  = (const float*)d_in[7];
    const float* fbih  = (const float*)d_in[8];
    const float* fbhh  = (const float*)d_in[9];
    const float* aWih  = (const float*)d_in[10];
    const float* aWhh  = (const float*)d_in[11];
    const float* abih  = (const float*)d_in[12];
    const float* abhh  = (const float*)d_in[13];
    const float* sw    = (const float*)d_in[14];
    const float* ew    = (const float*)d_in[15];
    const float* W1    = (const float*)d_in[16];
    const float* b1    = (const float*)d_in[17];
    const float* W2    = (const float*)d_in[18];
    const float* b2    = (const float*)d_in[19];
    const float* W3    = (const float*)d_in[20];
    const float* b3    = (const float*)d_in[21];
    float* outp = (float*)d_out;

    k_pre_tr<<<544, 256>>>(emb, tp, pred, al_p, kern, fWih, fWhh);
    k_gi<<<dim3(32, 7), 384>>>(fbih, anc);
    k_gru<<<NA, 384>>>(anc, fbhh, aWih, aWhh, abih, abhh, al_p,
                       W1, b1, W2, b2, W3, b3, sw, ew, outp);
}

// round 16
// speedup vs baseline: 1.0834x; 1.0501x over previous
#include <cuda_runtime.h>
#include <math.h>

#define N_NODES 512
#define DIM 128
#define NA 192          // total anchors
#define G3 384          // 3*DIM
typedef unsigned long long ULL;

// ---------------- scratch (no allocations allowed) ----------------
__device__ float g_x[N_NODES * DIM];
__device__ float g_abn[N_NODES];
__device__ float g_tpos[N_NODES];
__device__ float g_Gi[6 * N_NODES * G3];
__device__ float g_hout[NA * 2 * DIM];
__device__ float g_abnout[NA * 2];
__device__ float g_WihT[6 * DIM * G3];   // [sd][k][row]
__device__ float g_WhhT[6 * DIM * G3];   // [sd][k][row]
__device__ int   g_pairs[96][2];         // [scale*32+pair][2], len-matched within scale
__device__ int   g_order[96];            // pair schedule, len desc

__device__ __forceinline__ float sigf(float x) { return 1.f / (1.f + __expf(-x)); }
__device__ __forceinline__ float tanhfast(float x) { return 2.f / (1.f + __expf(-2.f * x)) - 1.f; }

// ---------------- kernel 1 (fused): preprocess + GRU weight transpose ----------------
__global__ void k_pre_tr(const float* __restrict__ emb, const float* __restrict__ tp,
                         const float* __restrict__ pred, const float* __restrict__ al_p,
                         const float* __restrict__ kern,
                         const float* __restrict__ Wih, const float* __restrict__ Whh)
{
    int b = blockIdx.x;
    int t = threadIdx.x;
    if (b < 256) {
        int tid = b * 256 + t;
        if (tid < N_NODES * DIM) {
            int n = tid >> 7, d = tid & 127;
            float freq = (10.f / 127.f) * (float)d;
            g_x[tid] = emb[tid] + 0.05f * sinf(tp[n] * freq);
        }
        if (tid < N_NODES) {
            int n = tid;
            float kv[5];
            #pragma unroll
            for (int k = 0; k < 5; k++) kv[k] = kern[k];
            float sv[5];
            #pragma unroll
            for (int c = 0; c < 5; c++) {
                float acc = 0.f;
                #pragma unroll
                for (int k = 0; k < 5; k++) {
                    int nn = n + k - 2;
                    if (nn >= 0 && nn < N_NODES) acc += kv[k] * pred[nn * 5 + c];
                }
                sv[c] = acc;
            }
            float m = sv[0];
            #pragma unroll
            for (int c = 1; c < 5; c++) m = fmaxf(m, sv[c]);
            float den = 0.f;
            #pragma unroll
            for (int c = 0; c < 5; c++) den += __expf(sv[c] - m);
            g_abn[n] = __expf(sv[0] - m) / den;
            g_tpos[n] = tp[n] * al_p[0];
        }
        return;
    }
    // GRU weight transpose (tiled, coalesced both sides)
    __shared__ float s1[32][33];
    __shared__ float s2[32][33];
    int bb = b - 256;
    int sd = bb / 48, bx = bb % 48;
    int ktile = bx & 3, rtile = bx >> 2;
    int x = t & 31, y = t >> 5;
    size_t base = (size_t)sd * G3 * DIM;
    #pragma unroll
    for (int j = 0; j < 4; j++) {
        int r = rtile * 32 + y * 4 + j;
        s1[y * 4 + j][x] = Wih[base + (size_t)r * DIM + ktile * 32 + x];
        s2[y * 4 + j][x] = Whh[base + (size_t)r * DIM + ktile * 32 + x];
    }
    __syncthreads();
    size_t obase = (size_t)sd * DIM * G3;
    #pragma unroll
    for (int j = 0; j < 4; j++) {
        int k = ktile * 32 + y * 4 + j;
        g_WihT[obase + (size_t)k * G3 + rtile * 32 + x] = s1[x][y * 4 + j];
        g_WhhT[obase + (size_t)k * G3 + rtile * 32 + x] = s2[x][y * 4 + j];
    }
}

// ---------------- kernel 2: Gi precompute (32-node chunks, single wave) + pair ranking ----------------
__global__ __launch_bounds__(384) void k_gi(const float* __restrict__ bih,
                                            const float* __restrict__ anchors)
{
    int t = threadIdx.x;
    if (blockIdx.y == 6) {
        if (blockIdx.x != 0) return;
        __shared__ float tps[N_NODES];
        __shared__ int lens[NA];
        __shared__ int plen[96];
        for (int i = t; i < N_NODES; i += 384) tps[i] = g_tpos[i];
        __syncthreads();
        if (t < NA) {
            float stt = anchors[2 * t], enn = anchors[2 * t + 1];
            int c = 0;
            for (int n = 0; n < N_NODES; n++)
                c += (tps[n] >= stt && tps[n] <= enn) ? 1 : 0;
            lens[t] = c;
        }
        __syncthreads();
        if (t < NA) {
            int s = t >> 6, base = s * 64;
            int L = lens[t];
            int r = 0;
            for (int j = 0; j < 64; j++) {
                int Lj = lens[base + j];
                if (Lj > L || (Lj == L && base + j < t)) r++;
            }
            g_pairs[s * 32 + (r >> 1)][r & 1] = t;
            if ((r & 1) == 0) plen[s * 32 + (r >> 1)] = L;
        }
        __syncthreads();
        if (t < 96) {
            int L = plen[t];
            int g = 0;
            for (int j = 0; j < 96; j++) {
                int Lj = plen[j];
                if (Lj > L || (Lj == L && j < t)) g++;
            }
            g_order[g] = t;
        }
        return;
    }

    int sd = blockIdx.y, chunk = blockIdx.x;          // 16 chunks of 32 nodes
    __shared__ __align__(16) float sx[32 * DIM];
    const float4* src = (const float4*)(g_x + (size_t)chunk * 32 * DIM);
    for (int i = t; i < 32 * DIM / 4; i += 384) ((float4*)sx)[i] = src[i];

    const float* wt = g_WihT + (size_t)sd * DIM * G3 + t;
    ULL w[64];
    #pragma unroll
    for (int k = 0; k < 64; k++) {
        float w0 = wt[(size_t)(2 * k) * G3];
        float w1 = wt[(size_t)(2 * k + 1) * G3];
        asm("mov.b64 %0,{%1,%2};" : "=l"(w[k]) : "f"(w0), "f"(w1));
    }
    float b = bih[sd * G3 + t];
    unsigned xb;
    asm("{.reg .u64 t0; cvta.to.shared.u64 t0,%1; cvt.u32.u64 %0,t0;}" : "=r"(xb) : "l"((float*)sx));
    __syncthreads();

    float* outp = g_Gi + ((size_t)sd * N_NODES + chunk * 32) * G3 + t;
    #pragma unroll 2
    for (int n = 0; n < 32; n++) {
        ULL acA = 0ull, acB = 0ull;
        unsigned base = xb + n * 512;
        #pragma unroll
        for (int i = 0; i < 16; i++) {
            ULL p0, p1, p2, p3;
            asm volatile("ld.shared.v2.b64 {%0,%1},[%2];" : "=l"(p0), "=l"(p1) : "r"(base + i * 32));
            asm volatile("ld.shared.v2.b64 {%0,%1},[%2];" : "=l"(p2), "=l"(p3) : "r"(base + i * 32 + 16));
            asm("fma.rn.f32x2 %0,%1,%2,%0;" : "+l"(acA) : "l"(w[4 * i])     , "l"(p0));
            asm("fma.rn.f32x2 %0,%1,%2,%0;" : "+l"(acB) : "l"(w[4 * i + 1]) , "l"(p1));
            asm("fma.rn.f32x2 %0,%1,%2,%0;" : "+l"(acA) : "l"(w[4 * i + 2]) , "l"(p2));
            asm("fma.rn.f32x2 %0,%1,%2,%0;" : "+l"(acB) : "l"(w[4 * i + 3]) , "l"(p3));
        }
        float a0, a1, b0, b1;
        asm("mov.b64 {%0,%1},%2;" : "=f"(a0), "=f"(a1) : "l"(acA));
        asm("mov.b64 {%0,%1},%2;" : "=f"(b0), "=f"(b1) : "l"(acB));
        outp[(size_t)n * G3] = ((a0 + a1) + (b0 + b1)) + b;
    }
}

// ---------------- kernel 3: GRU, 2 len-matched anchors/block, 4 acc chains (r9) ----------------
__global__ __launch_bounds__(384, 1) void k_gru(const float* __restrict__ anchors,
                                                const float* __restrict__ bhh,
                                                const float* __restrict__ aWih,
                                                const float* __restrict__ aWhh,
                                                const float* __restrict__ abih,
                                                const float* __restrict__ abhh)
{
    int t = threadIdx.x;
    __shared__ int sh_task[4];
    __shared__ __align__(16) float sh_h[2][DIM];
    __shared__ float ghA[G3];
    __shared__ float ghB[G3];
    __shared__ unsigned short idxAB[2][N_NODES];
    __shared__ int sh_len[2];
    __shared__ float sh_abh[2];
    __shared__ float aw[12];

    if (t == 0) {
        int pr = g_order[blockIdx.x >> 1];
        sh_task[0] = g_pairs[pr][0];
        sh_task[1] = g_pairs[pr][1];
        sh_task[2] = pr >> 5;
        sh_task[3] = blockIdx.x & 1;
    }
    __syncthreads();
    int aA = sh_task[0], aB = sh_task[1], s = sh_task[2], dir = sh_task[3];
    int sd = s * 2 + dir;

    int wid = t >> 5, lane = t & 31;
    if (wid < 2) {
        int aa = wid ? aB : aA;
        float stt = anchors[2 * aa], enn = anchors[2 * aa + 1];
        unsigned short* ix = idxAB[wid];
        int off = 0;
        for (int base = 0; base < N_NODES; base += 32) {
            int n = base + lane;
            float tp = g_tpos[n];
            bool m = (tp >= stt) && (tp <= enn);
            unsigned bal = __ballot_sync(0xffffffffu, m);
            if (m) ix[off + __popc(bal & ((1u << lane) - 1u))] = (unsigned short)n;
            off += __popc(bal);
        }
        if (dir) {
            for (int i = lane; i < (off >> 1); i += 32) {
                unsigned short tmp = ix[i];
                ix[i] = ix[off - 1 - i];
                ix[off - 1 - i] = tmp;
            }
        }
        if (lane == 0) { sh_len[wid] = off; sh_abh[wid] = 0.f; }
    }
    if (t < DIM) { sh_h[0][t] = 0.f; sh_h[1][t] = 0.f; }
    {
        int base = sd * 3;
        if (t >= 64 && t < 67)  aw[t - 64]      = aWih[base + t - 64];
        if (t >= 67 && t < 70)  aw[3 + t - 67]  = aWhh[base + t - 67];
        if (t >= 70 && t < 73)  aw[6 + t - 70]  = abih[base + t - 70];
        if (t >= 73 && t < 76)  aw[9 + t - 73]  = abhh[base + t - 73];
    }

    const float* wt = g_WhhT + (size_t)sd * DIM * G3 + t;
    ULL w[64];
    #pragma unroll
    for (int k = 0; k < 64; k++) {
        float w0 = wt[(size_t)(2 * k) * G3];
        float w1 = wt[(size_t)(2 * k + 1) * G3];
        asm("mov.b64 %0,{%1,%2};" : "=l"(w[k]) : "f"(w0), "f"(w1));
    }
    float bh = bhh[sd * G3 + t];

    unsigned hb;
    asm("{.reg .u64 t0; cvta.to.shared.u64 t0,%1; cvt.u32.u64 %0,t0;}" : "=r"(hb) : "l"(&sh_h[0][0]));
    __syncthreads();

    int lenA = sh_len[0], lenB = sh_len[1];
    int L = lenA > lenB ? lenA : lenB;
    const float* Gi = g_Gi + (size_t)sd * N_NODES * G3;

    bool roleA = (t < 128);
    bool roleB = (t >= 128 && t < 256);
    int tt = t & 127;
    int mylen = roleA ? lenA : (roleB ? lenB : 0);
    const unsigned short* myidx = roleA ? idxAB[0] : idxAB[1];

    float c0 = 0.f, c1 = 0.f, c2 = 0.f;
    if ((roleA || roleB) && mylen > 0) {
        const float* gp = Gi + (size_t)myidx[0] * G3;
        c0 = gp[tt]; c1 = gp[DIM + tt]; c2 = gp[2 * DIM + tt];
    }
    float abc = 0.f;
    if (t == 256 && lenA > 0) abc = g_abn[idxAB[0][0]];
    if (t == 257 && lenB > 0) abc = g_abn[idxAB[1][0]];

    for (int step = 0; step < L; step++) {
        float n0 = 0.f, n1 = 0.f, n2 = 0.f, abn_next = 0.f;
        int sn = step + 1;
        if ((roleA || roleB) && sn < mylen) {
            const float* gp = Gi + (size_t)myidx[sn] * G3;
            n0 = gp[tt]; n1 = gp[DIM + tt]; n2 = gp[2 * DIM + tt];
        }
        if (t == 256 && sn < lenA) abn_next = g_abn[idxAB[0][sn]];
        if (t == 257 && sn < lenB) abn_next = g_abn[idxAB[1][sn]];

        ULL accA0 = 0ull, accA1 = 0ull, accB0 = 0ull, accB1 = 0ull;
        #pragma unroll
        for (int i = 0; i < 32; i++) {
            ULL a0, a1, b0, b1;
            asm volatile("ld.shared.v2.b64 {%0,%1},[%2];" : "=l"(a0), "=l"(a1) : "r"(hb + i * 16));
            asm volatile("ld.shared.v2.b64 {%0,%1},[%2];" : "=l"(b0), "=l"(b1) : "r"(hb + 512 + i * 16));
            asm("fma.rn.f32x2 %0,%1,%2,%0;" : "+l"(accA0) : "l"(w[2 * i])     , "l"(a0));
            asm("fma.rn.f32x2 %0,%1,%2,%0;" : "+l"(accB0) : "l"(w[2 * i])     , "l"(b0));
            asm("fma.rn.f32x2 %0,%1,%2,%0;" : "+l"(accA1) : "l"(w[2 * i + 1]) , "l"(a1));
            asm("fma.rn.f32x2 %0,%1,%2,%0;" : "+l"(accB1) : "l"(w[2 * i + 1]) , "l"(b1));
        }
        float pa0, pa1, pa2, pa3, pb0, pb1, pb2, pb3;
        asm("mov.b64 {%0,%1},%2;" : "=f"(pa0), "=f"(pa1) : "l"(accA0));
        asm("mov.b64 {%0,%1},%2;" : "=f"(pa2), "=f"(pa3) : "l"(accA1));
        asm("mov.b64 {%0,%1},%2;" : "=f"(pb0), "=f"(pb1) : "l"(accB0));
        asm("mov.b64 {%0,%1},%2;" : "=f"(pb2), "=f"(pb3) : "l"(accB1));
        ghA[t] = ((pa0 + pa1) + (pa2 + pa3)) + bh;
        ghB[t] = ((pb0 + pb1) + (pb2 + pb3)) + bh;
        __syncthreads();

        bool actA = step < lenA, actB = step < lenB;
        if (roleA) {
            if (actA) {
                float r  = sigf(c0 + ghA[tt]);
                float z  = sigf(c1 + ghA[DIM + tt]);
                float nn = tanhfast(c2 + r * ghA[2 * DIM + tt]);
                sh_h[0][tt] = (1.f - z) * nn + z * sh_h[0][tt];
            }
        } else if (roleB) {
            if (actB) {
                float r  = sigf(c0 + ghB[tt]);
                float z  = sigf(c1 + ghB[DIM + tt]);
                float nn = tanhfast(c2 + r * ghB[2 * DIM + tt]);
                sh_h[1][tt] = (1.f - z) * nn + z * sh_h[1][tt];
            }
        } else if (t == 256) {
            if (actA) {
                float h = sh_abh[0];
                float r  = sigf(aw[0] * abc + aw[6] + aw[3] * h + aw[9]);
                float z  = sigf(aw[1] * abc + aw[7] + aw[4] * h + aw[10]);
                float nn = tanhfast(aw[2] * abc + aw[8] + r * (aw[5] * h + aw[11]));
                sh_abh[0] = (1.f - z) * nn + z * h;
            }
        } else if (t == 257) {
            if (actB) {
                float h = sh_abh[1];
                float r  = sigf(aw[0] * abc + aw[6] + aw[3] * h + aw[9]);
                float z  = sigf(aw[1] * abc + aw[7] + aw[4] * h + aw[10]);
                float nn = tanhfast(aw[2] * abc + aw[8] + r * (aw[5] * h + aw[11]));
                sh_abh[1] = (1.f - z) * nn + z * h;
            }
        }
        c0 = n0; c1 = n1; c2 = n2; abc = abn_next;
        __syncthreads();
    }

    if (roleA)      g_hout[((size_t)aA * 2 + dir) * DIM + tt] = sh_h[0][tt];
    else if (roleB) g_hout[((size_t)aB * 2 + dir) * DIM + tt] = sh_h[1][tt];
    else if (t == 256) g_abnout[aA * 2 + dir] = sh_abh[0];
    else if (t == 257) g_abnout[aB * 2 + dir] = sh_abh[1];
}

// ---------------- kernel 4: MLP head (r9 best variant) ----------------
__global__ __launch_bounds__(256) void k_head(const float* __restrict__ anchors,
                                              const float* __restrict__ al_p,
                                              const float* __restrict__ W1, const float* __restrict__ b1,
                                              const float* __restrict__ W2, const float* __restrict__ b2,
                                              const float* __restrict__ W3, const float* __restrict__ b3,
                                              const float* __restrict__ start_w,
                                              const float* __restrict__ end_w,
                                              float* __restrict__ out)
{
    int a = blockIdx.x;
    int s = a >> 6;
    int t = threadIdx.x;
    const int FIN = 2 * DIM + 3;   // 259
    const int FOUT = 47;

    __shared__ float sf[FIN + 1];
    __shared__ float h1[256];
    __shared__ float h2[256];
    __shared__ float o[FOUT + 1];
    __shared__ float soeo[2];

    float al = al_p[0];
    if (t < DIM) {
        sf[t]       = g_hout[((size_t)a * 2 + 0) * DIM + t];
        sf[DIM + t] = g_hout[((size_t)a * 2 + 1) * DIM + t];
    }
    if (t == 0) {
        sf[256] = 0.5f * (g_abnout[a * 2] + g_abnout[a * 2 + 1]);
        float stt = anchors[a * 2], enn = anchors[a * 2 + 1];
        sf[257] = (stt + enn) * 0.5f / al;
        sf[258] = (enn - stt) / al;
    }
    __syncthreads();

    {
        const float* W = W1 + (size_t)s * FIN * 256 + t;
        float acc[8];
        #pragma unroll
        for (int q = 0; q < 8; q++) acc[q] = 0.f;
        float wreg[64];
        #pragma unroll
        for (int p = 0; p < 4; p++) {
            int i0 = p * 64;
            #pragma unroll
            for (int j = 0; j < 64; j++) wreg[j] = W[(size_t)(i0 + j) * 256];
            #pragma unroll
            for (int j = 0; j < 64; j++) acc[j & 7] += wreg[j] * sf[i0 + j];
        }
        acc[0] += W[(size_t)256 * 256] * sf[256];
        acc[1] += W[(size_t)257 * 256] * sf[257];
        acc[2] += W[(size_t)258 * 256] * sf[258];
        float r = (((acc[0] + acc[1]) + (acc[2] + acc[3])) + ((acc[4] + acc[5]) + (acc[6] + acc[7])))
                  + b1[s * 256 + t];
        h1[t] = fmaxf(r, 0.f);
    }
    __syncthreads();

    {
        const float* W = W2 + (size_t)s * 256 * 256 + t;
        float acc[8];
        #pragma unroll
        for (int q = 0; q < 8; q++) acc[q] = 0.f;
        float wreg[64];
        #pragma unroll
        for (int p = 0; p < 4; p++) {
            int i0 = p * 64;
            #pragma unroll
            for (int j = 0; j < 64; j++) wreg[j] = W[(size_t)(i0 + j) * 256];
            #pragma unroll
            for (int j = 0; j < 64; j++) acc[j & 7] += wreg[j] * h1[i0 + j];
        }
        float r = (((acc[0] + acc[1]) + (acc[2] + acc[3])) + ((acc[4] + acc[5]) + (acc[6] + acc[7])))
                  + b2[s * 256 + t];
        h2[t] = fmaxf(r, 0.f);
    }
    __syncthreads();

    if (t < FOUT) {
        const float* W = W3 + (size_t)s * 256 * FOUT + t;
        float acc[8];
        #pragma unroll
        for (int q = 0; q < 8; q++) acc[q] = 0.f;
        float wreg[64];
        #pragma unroll
        for (int p = 0; p < 4; p++) {
            int i0 = p * 64;
            #pragma unroll
            for (int j = 0; j < 64; j++) wreg[j] = W[(size_t)(i0 + j) * FOUT];
            #pragma unroll
            for (int j = 0; j < 64; j++) acc[j & 7] += wreg[j] * h2[i0 + j];
        }
        o[t] = (((acc[0] + acc[1]) + (acc[2] + acc[3])) + ((acc[4] + acc[5]) + (acc[6] + acc[7])))
               + b3[s * FOUT + t];
    }
    __syncthreads();

    if (t < 2) {
        const float* wv = (t == 0) ? (start_w + s * 21) : (end_w + s * 21);
        const float* ov = o + t * 21;
        float m = -1e30f;
        for (int j = 0; j < 21; j++) m = fmaxf(m, ov[j]);
        float den = 0.f, num = 0.f;
        for (int j = 0; j < 21; j++) { float e = __expf(ov[j] - m); den += e; num += e * wv[j]; }
        soeo[t] = num / den;
    }
    __syncthreads();

    if (t == 0) {
        float stt = anchors[a * 2], enn = anchors[a * 2 + 1];
        out[a * 2]      = fminf(fmaxf(stt + soeo[0], 0.f), al);
        out[a * 2 + 1]  = fminf(fmaxf(enn + soeo[1], 0.f), al);
        out[2 * NA + a] = o[42];
    }
    if (t < 4) out[3 * NA + a * 4 + t] = o[43 + t];
}

// ---------------- launcher ----------------
extern "C" void kernel_launch(void* const* d_in, const int* in_sizes, int n_in,
                              void* d_out, int out_size)
{
    const float* emb   = (const float*)d_in[0];
    const float* tp    = (const float*)d_in[1];
    const float* pred  = (const float*)d_in[2];
    const float* al_p  = (const float*)d_in[3];
    const float* anc   = (const float*)d_in[4];
    const float* kern  = (const float*)d_in[5];
    const float* fWih  = (const float*)d_in[6];
    const float* fWhh  = (const float*)d_in[7];
    const float* fbih  = (const float*)d_in[8];
    const float* fbhh  = (const float*)d_in[9];
    const float* aWih  = (const float*)d_in[10];
    const float* aWhh  = (const float*)d_in[11];
    const float* abih  = (const float*)d_in[12];
    const float* abhh  = (const float*)d_in[13];
    const float* sw    = (const float*)d_in[14];
    const float* ew    = (const float*)d_in[15];
    const float* W1    = (const float*)d_in[16];
    const float* b1    = (const float*)d_in[17];
    const float* W2    = (const float*)d_in[18];
    const float* b2    = (const float*)d_in[19];
    const float* W3    = (const float*)d_in[20];
    const float* b3    = (const float*)d_in[21];
    float* outp = (float*)d_out;

    k_pre_tr<<<544, 256>>>(emb, tp, pred, al_p, kern, fWih, fWhh);
    k_gi<<<dim3(16, 7), 384>>>(fbih, anc);
    k_gru<<<NA, 384>>>(anc, fbhh, aWih, aWhh, abih, abhh);
    k_head<<<NA, 256>>>(anc, al_p, W1, b1, W2, b2, W3, b3, sw, ew, outp);
}